// round 8
// baseline (speedup 1.0000x reference)
#include <cuda_runtime.h>
#include <cstdint>

#define NE 256
#define NC 48
#define NB 64
#define NT 1024
#define ROWS 128
#define KT   32
#define PADW 36          // 36 % 32 == 4 -> conflict-free strided LDS
#define NTILES 512       // (NB*NT)/ROWS
#define BUF_FLOATS 6336  // fcw 48*36 + emb 128*36
#define GEMM_SMEM (2 * BUF_FLOATS * 4 + ROWS * 4)

static __device__ float g_partial[NB];
static __device__ int   g_done;                // zero-init; self-resets each run

// ---------- packed f32x2 helpers ----------
__device__ __forceinline__ unsigned long long ffma2(unsigned long long a, unsigned long long b,
                                                    unsigned long long c) {
    unsigned long long d;
    asm("fma.rn.f32x2 %0, %1, %2, %3;" : "=l"(d) : "l"(a), "l"(b), "l"(c));
    return d;
}
__device__ __forceinline__ unsigned long long fadd2(unsigned long long a, unsigned long long b) {
    unsigned long long d;
    asm("add.rn.f32x2 %0, %1, %2;" : "=l"(d) : "l"(a), "l"(b));
    return d;
}
__device__ __forceinline__ float2 unpack2(unsigned long long a) {
    float2 f;
    asm("mov.b64 {%0, %1}, %2;" : "=f"(f.x), "=f"(f.y) : "l"(a));
    return f;
}
__device__ __forceinline__ unsigned long long pack2(float x, float y) {
    unsigned long long d;
    asm("mov.b64 %0, {%1, %2};" : "=l"(d) : "f"(x), "f"(y));
    return d;
}
__device__ __forceinline__ float frcp_fast(float x) {
    float r; asm("rcp.approx.f32 %0, %1;" : "=f"(r) : "f"(x)); return r;
}
__device__ __forceinline__ uint32_t smem_u32(const void* p) {
    uint32_t a;
    asm("{ .reg .u64 t; cvta.to.shared.u64 t, %1; cvt.u32.u64 %0, t; }" : "=r"(a) : "l"(p));
    return a;
}
__device__ __forceinline__ void ldgsts16(uint32_t dst, const void* src) {
    asm volatile("cp.async.cg.shared.global [%0], [%1], 16;" :: "r"(dst), "l"(src));
}

// ============================================================================
// Kernel 1: logits = gather(emb)[65536x256] @ fc_w^T[48x256] + fc_b
// 256 threads, 3 blocks/SM, thread tile 4x6, K split into 8 tiles of 32,
// cp.async double-buffered. (unchanged from R7 — measured good)
// ============================================================================
__global__ __launch_bounds__(256, 3) void gemm_kernel(
    const int* __restrict__ x, const float* __restrict__ emb,
    const float* __restrict__ fcw, const float* __restrict__ fcb,
    float* __restrict__ out)
{
    extern __shared__ float sm[];
    int* x_s = (int*)(sm + 2 * BUF_FLOATS);

    const int tid = threadIdx.x;
    const int rowBase = blockIdx.x * ROWS;
    if (tid < ROWS) x_s[tid] = x[rowBase + tid];
    __syncthreads();

    const uint32_t smbase = smem_u32(sm);

    #define LOAD_TILE(KIDX, BUF)                                               \
    {                                                                          \
        const int k0 = (KIDX) * KT;                                            \
        const uint32_t fb  = smbase + (BUF) * BUF_FLOATS * 4;                  \
        const uint32_t ebs = fb + 1728 * 4;                                    \
        for (int i = tid; i < 384; i += 256) {                                 \
            int r = i >> 3, k4 = i & 7;                                        \
            ldgsts16(fb + (r * PADW + 4 * k4) * 4, fcw + r * NE + k0 + 4 * k4);\
        }                                                                      \
        for (int i = tid; i < 1024; i += 256) {                                \
            int r = i >> 3, k4 = i & 7;                                        \
            ldgsts16(ebs + (r * PADW + 4 * k4) * 4,                            \
                     emb + (size_t)x_s[r] * NE + k0 + 4 * k4);                 \
        }                                                                      \
        asm volatile("cp.async.commit_group;");                                \
    }

    LOAD_TILE(0, 0);

    const int tx = tid & 7;
    const int ty = tid >> 3;

    unsigned long long acc[4][6];
    #pragma unroll
    for (int m = 0; m < 4; m++)
        #pragma unroll
        for (int n = 0; n < 6; n++) acc[m][n] = 0ull;

    for (int kt = 0; kt < 8; kt++) {
        if (kt < 7) {
            LOAD_TILE(kt + 1, (kt + 1) & 1);
            asm volatile("cp.async.wait_group %0;" :: "n"(1));
        } else {
            asm volatile("cp.async.wait_group %0;" :: "n"(0));
        }
        __syncthreads();

        const float* fcw_s = sm + (kt & 1) * BUF_FLOATS;
        const float* emb_s = fcw_s + 1728;

        #pragma unroll 4
        for (int k2 = 0; k2 < KT / 2; k2++) {
            unsigned long long a2[4], w2[6];
            #pragma unroll
            for (int m = 0; m < 4; m++)
                a2[m] = *(const unsigned long long*)&emb_s[(ty + 32 * m) * PADW + 2 * k2];
            #pragma unroll
            for (int n = 0; n < 6; n++)
                w2[n] = *(const unsigned long long*)&fcw_s[(tx + 8 * n) * PADW + 2 * k2];
            #pragma unroll
            for (int m = 0; m < 4; m++)
                #pragma unroll
                for (int n = 0; n < 6; n++)
                    acc[m][n] = ffma2(a2[m], w2[n], acc[m][n]);
        }
        __syncthreads();
    }
    #undef LOAD_TILE

    #pragma unroll
    for (int m = 0; m < 4; m++) {
        int r = rowBase + ty + 32 * m;
        #pragma unroll
        for (int n = 0; n < 6; n++) {
            int c = tx + 8 * n;
            float2 p = unpack2(acc[m][n]);
            out[(size_t)r * NC + c] = p.x + p.y + __ldg(&fcb[c]);
        }
    }
}

// ============================================================================
// Kernel 2: CRF forward scan — split-K version. 96 threads = 3 warps.
// thread = (state c = tid>>1, half h = tid&1). Each thread: 6 LDS.128 +
// 12 FFMA2 over its 24-input half; halves combined with shfl.bfly(1)
// (partners tid 2c/2c+1 always in the same warp). Even lane stores alpha.
// Flat 4-step-unrolled loop, in-step branchless renorm, in-loop __expf
// (R2-proven loop shape). Fused last-block final reduce.
// ============================================================================
__global__ __launch_bounds__(96) void crf_kernel(
    const float* __restrict__ logits,
    const int* __restrict__ labels,
    const float* __restrict__ start_trans,
    const float* __restrict__ end_trans,
    const float* __restrict__ trans,
    float* __restrict__ out, int out_size)
{
    __shared__ __align__(16) float a_sh[2][64];
    __shared__ float red[96];

    const int b   = blockIdx.x;
    const int tid = threadIdx.x;
    const float* lg  = logits + (size_t)b * NT * NC;
    const int*   lab = labels + b * NT;

    // ---- numerator (parallel over t, fixed-order reduce) ----
    float acc = 0.f;
    for (int t = tid; t < NT; t += 96) {
        int lt = lab[t];
        acc += lg[t * NC + lt];
        if (t + 1 < NT) acc += trans[lt * NC + lab[t + 1]];
    }
    if (tid == 0)  acc += start_trans[lab[0]];
    if (tid == 95) acc += end_trans[lab[NT - 1]];
    red[tid] = acc;
    __syncthreads();
    float num = 0.f;
    if (tid == 0) {
        #pragma unroll
        for (int i = 0; i < 96; i++) num += red[i];
    }

    // ---- per-thread (state, half) setup ----
    const int c    = tid >> 1;        // 0..47
    const int h    = tid & 1;         // input half
    const int base = 24 * h;          // inputs [base, base+24)

    unsigned long long Eh[12];
    #pragma unroll
    for (int k = 0; k < 12; k++) {
        float e0 = __expf(trans[(base + 2 * k)     * NC + c]) * 0.015625f;  // /64
        float e1 = __expf(trans[(base + 2 * k + 1) * NC + c]) * 0.015625f;
        Eh[k] = pack2(e0, e1);
    }
    float a_cur = __expf(start_trans[c] + lg[c]);
    if (h == 0) a_sh[0][c] = a_cur;

    float logscale = 0.f;

    float eb[4];
    #pragma unroll
    for (int jj = 0; jj < 4; jj++) eb[jj] = lg[(1 + jj) * NC + c];
    __syncthreads();

    int p = 0;

    #define CRF_STEP(T, EMIS)                                                  \
    {                                                                          \
        float ex = __expf(EMIS);                                               \
        float r  = a_sh[p][0];                                                 \
        unsigned long long s0 = 0ull, s1 = 0ull, s2 = 0ull, s3 = 0ull;         \
        _Pragma("unroll")                                                      \
        for (int jj = 0; jj < 3; jj++) {                                       \
            ulonglong2 u = *(const ulonglong2*)&a_sh[p][base + 8 * jj];        \
            ulonglong2 v = *(const ulonglong2*)&a_sh[p][base + 8 * jj + 4];    \
            s0 = ffma2(u.x, Eh[4 * jj],     s0);                               \
            s1 = ffma2(u.y, Eh[4 * jj + 1], s1);                               \
            s2 = ffma2(v.x, Eh[4 * jj + 2], s2);                               \
            s3 = ffma2(v.y, Eh[4 * jj + 3], s3);                               \
        }                                                                      \
        float2 sp = unpack2(fadd2(fadd2(s0, s2), fadd2(s1, s3)));              \
        float half = sp.x + sp.y;                                              \
        float s = half + __shfl_xor_sync(0xffffffffu, half, 1);                \
        bool rn = ((T) & 127) == 0;                                            \
        float sel = rn ? frcp_fast(r) : 1.0f;                                  \
        logscale += rn ? __logf(r) : 0.0f;                                     \
        float anew = s * ex * sel;                                             \
        if (h == 0) a_sh[p ^ 1][c] = anew;                                     \
        a_cur = anew;                                                          \
        __syncthreads();                                                       \
        p ^= 1;                                                                \
    }

    // main loop: t = 1 .. 1020, groups of 4, no interior branches
    for (int tb = 1; tb + 3 < NT; tb += 4) {
        float en[4];
        #pragma unroll
        for (int jj = 0; jj < 4; jj++) {
            int tt = tb + 4 + jj;
            tt = (tt < NT) ? tt : (NT - 1);
            en[jj] = lg[tt * NC + c];
        }
        CRF_STEP(tb + 0, eb[0]);
        CRF_STEP(tb + 1, eb[1]);
        CRF_STEP(tb + 2, eb[2]);
        CRF_STEP(tb + 3, eb[3]);
        eb[0] = en[0]; eb[1] = en[1]; eb[2] = en[2]; eb[3] = en[3];
    }
    // epilogue: t = 1021, 1022, 1023
    CRF_STEP(NT - 3, eb[0]);
    CRF_STEP(NT - 2, eb[1]);
    CRF_STEP(NT - 1, eb[2]);
    #undef CRF_STEP

    // ---- logZ + per-chain partial; last block reduces everything ----
    if (h == 0) red[c] = a_cur * __expf(end_trans[c]);
    __syncthreads();
    if (tid == 0) {
        float s = 0.f;
        #pragma unroll
        for (int i = 0; i < NC; i++) s += red[i];
        float logz = __logf(s) + logscale + 4254.5374f;   // + 1023*ln(64)
        g_partial[b] = num - logz;
        __threadfence();
        int v = atomicAdd(&g_done, 1);
        if (v == NB - 1) {                 // last chain: final reduce
            float tot = 0.f;
            #pragma unroll
            for (int i = 0; i < NB; i++) tot += g_partial[i];
            out[out_size - 1] = -tot;
            atomicExch(&g_done, 0);        // reset for graph replay
        }
    }
}

extern "C" void kernel_launch(void* const* d_in, const int* in_sizes, int n_in,
                              void* d_out, int out_size)
{
    const int*   x    = (const int*)  d_in[0];
    const int*   lab  = (const int*)  d_in[1];
    const float* emb  = (const float*)d_in[2];
    const float* fcw  = (const float*)d_in[3];
    const float* fcb  = (const float*)d_in[4];
    const float* st   = (const float*)d_in[5];
    const float* et   = (const float*)d_in[6];
    const float* tr   = (const float*)d_in[7];
    float* out = (float*)d_out;

    cudaFuncSetAttribute(gemm_kernel, cudaFuncAttributeMaxDynamicSharedMemorySize, GEMM_SMEM);
    gemm_kernel<<<NTILES, 256, GEMM_SMEM>>>(x, emb, fcw, fcb, out);
    crf_kernel<<<NB, 96>>>(out, lab, st, et, tr, out, out_size);
}

// round 9
// speedup vs baseline: 1.0598x; 1.0598x over previous
#include <cuda_runtime.h>
#include <cstdint>

#define NE 256
#define NC 48
#define NB 64
#define NT 1024
#define ROWS 128
#define KT   32
#define PADW 36          // 36 % 32 == 4 -> conflict-free strided LDS
#define NTILES 512       // (NB*NT)/ROWS
#define BUF_FLOATS 6336  // fcw 48*36 + emb 128*36
#define GEMM_SMEM (2 * BUF_FLOATS * 4 + ROWS * 4)

static __device__ float g_partial[NB];
static __device__ int   g_done;                // zero-init; self-resets each run

// ---------- packed f32x2 helpers ----------
__device__ __forceinline__ unsigned long long ffma2(unsigned long long a, unsigned long long b,
                                                    unsigned long long c) {
    unsigned long long d;
    asm("fma.rn.f32x2 %0, %1, %2, %3;" : "=l"(d) : "l"(a), "l"(b), "l"(c));
    return d;
}
__device__ __forceinline__ unsigned long long fadd2(unsigned long long a, unsigned long long b) {
    unsigned long long d;
    asm("add.rn.f32x2 %0, %1, %2;" : "=l"(d) : "l"(a), "l"(b));
    return d;
}
__device__ __forceinline__ float2 unpack2(unsigned long long a) {
    float2 f;
    asm("mov.b64 {%0, %1}, %2;" : "=f"(f.x), "=f"(f.y) : "l"(a));
    return f;
}
__device__ __forceinline__ unsigned long long pack2(float x, float y) {
    unsigned long long d;
    asm("mov.b64 %0, {%1, %2};" : "=l"(d) : "f"(x), "f"(y));
    return d;
}
__device__ __forceinline__ float frcp_fast(float x) {
    float r; asm("rcp.approx.f32 %0, %1;" : "=f"(r) : "f"(x)); return r;
}
__device__ __forceinline__ uint32_t smem_u32(const void* p) {
    uint32_t a;
    asm("{ .reg .u64 t; cvta.to.shared.u64 t, %1; cvt.u32.u64 %0, t; }" : "=r"(a) : "l"(p));
    return a;
}
__device__ __forceinline__ void ldgsts16(uint32_t dst, const void* src) {
    asm volatile("cp.async.cg.shared.global [%0], [%1], 16;" :: "r"(dst), "l"(src));
}

// ============================================================================
// Kernel 1: logits = gather(emb)[65536x256] @ fc_w^T[48x256] + fc_b
// 128 threads/block, thread tile 8x6 (fma-dense: 48 FFMA2 per 14 LDS.64),
// K split into 8 tiles of 32, cp.async double-buffered, 3 blocks/SM.
// ============================================================================
__global__ __launch_bounds__(128, 3) void gemm_kernel(
    const int* __restrict__ x, const float* __restrict__ emb,
    const float* __restrict__ fcw, const float* __restrict__ fcb,
    float* __restrict__ out)
{
    extern __shared__ float sm[];
    int* x_s = (int*)(sm + 2 * BUF_FLOATS);

    const int tid = threadIdx.x;
    const int rowBase = blockIdx.x * ROWS;
    x_s[tid] = x[rowBase + tid];
    __syncthreads();

    const uint32_t smbase = smem_u32(sm);

    #define LOAD_TILE(KIDX, BUF)                                               \
    {                                                                          \
        const int k0 = (KIDX) * KT;                                            \
        const uint32_t fb  = smbase + (BUF) * BUF_FLOATS * 4;                  \
        const uint32_t ebs = fb + 1728 * 4;                                    \
        for (int i = tid; i < 384; i += 128) {                                 \
            int r = i >> 3, k4 = i & 7;                                        \
            ldgsts16(fb + (r * PADW + 4 * k4) * 4, fcw + r * NE + k0 + 4 * k4);\
        }                                                                      \
        for (int i = tid; i < 1024; i += 128) {                                \
            int r = i >> 3, k4 = i & 7;                                        \
            ldgsts16(ebs + (r * PADW + 4 * k4) * 4,                            \
                     emb + (size_t)x_s[r] * NE + k0 + 4 * k4);                 \
        }                                                                      \
        asm volatile("cp.async.commit_group;");                                \
    }

    LOAD_TILE(0, 0);

    const int tx = tid & 7;   // col group 0..7
    const int ty = tid >> 3;  // row group 0..15

    unsigned long long acc[8][6];
    #pragma unroll
    for (int m = 0; m < 8; m++)
        #pragma unroll
        for (int n = 0; n < 6; n++) acc[m][n] = 0ull;

    for (int kt = 0; kt < 8; kt++) {
        if (kt < 7) {
            LOAD_TILE(kt + 1, (kt + 1) & 1);                   // prefetch next
            asm volatile("cp.async.wait_group %0;" :: "n"(1)); // tile kt ready
        } else {
            asm volatile("cp.async.wait_group %0;" :: "n"(0)); // all done
        }
        __syncthreads();

        const float* fcw_s = sm + (kt & 1) * BUF_FLOATS;
        const float* emb_s = fcw_s + 1728;

        #pragma unroll 2
        for (int k2 = 0; k2 < KT / 2; k2++) {
            unsigned long long a2[8], w2[6];
            #pragma unroll
            for (int m = 0; m < 8; m++)
                a2[m] = *(const unsigned long long*)&emb_s[(ty + 16 * m) * PADW + 2 * k2];
            #pragma unroll
            for (int n = 0; n < 6; n++)
                w2[n] = *(const unsigned long long*)&fcw_s[(tx + 8 * n) * PADW + 2 * k2];
            #pragma unroll
            for (int m = 0; m < 8; m++)
                #pragma unroll
                for (int n = 0; n < 6; n++)
                    acc[m][n] = ffma2(a2[m], w2[n], acc[m][n]);
        }
        __syncthreads();
    }
    #undef LOAD_TILE

    #pragma unroll
    for (int m = 0; m < 8; m++) {
        int r = rowBase + ty + 16 * m;
        #pragma unroll
        for (int n = 0; n < 6; n++) {
            int c = tx + 8 * n;
            float2 p = unpack2(acc[m][n]);
            out[(size_t)r * NC + c] = p.x + p.y + __ldg(&fcb[c]);
        }
    }
}

// ============================================================================
// Kernel 2: CRF forward scan — R7 structure (best measured ~105us bench).
// 64 threads, flat 4-step-unrolled loop, in-step branchless renorm,
// in-loop __expf, 4-step emission prefetch. Fused last-block final reduce.
// ============================================================================
__global__ __launch_bounds__(64) void crf_kernel(
    const float* __restrict__ logits,
    const int* __restrict__ labels,
    const float* __restrict__ start_trans,
    const float* __restrict__ end_trans,
    const float* __restrict__ trans,
    float* __restrict__ out, int out_size)
{
    __shared__ __align__(16) float a_sh[2][64];
    __shared__ float red[64];

    const int b   = blockIdx.x;
    const int tid = threadIdx.x;
    const float* lg  = logits + (size_t)b * NT * NC;
    const int*   lab = labels + b * NT;

    // ---- numerator (parallel over t, fixed-order reduce) ----
    float acc = 0.f;
    for (int t = tid; t < NT; t += 64) {
        int lt = lab[t];
        acc += lg[t * NC + lt];
        if (t + 1 < NT) acc += trans[lt * NC + lab[t + 1]];
    }
    if (tid == 0)  acc += start_trans[lab[0]];
    if (tid == 63) acc += end_trans[lab[NT - 1]];
    red[tid] = acc;
    __syncthreads();
    float num = 0.f;
    if (tid == 0) {
        #pragma unroll
        for (int i = 0; i < 64; i++) num += red[i];
    }

    // ---- branch-free setup: all 64 lanes compute with clamped state index ----
    const int cc = (tid < NC) ? tid : (NC - 1);

    unsigned long long Ec2[24];
    #pragma unroll
    for (int j = 0; j < 24; j++) {
        float e0 = __expf(trans[(2 * j)     * NC + cc]) * 0.015625f;  // /64
        float e1 = __expf(trans[(2 * j + 1) * NC + cc]) * 0.015625f;
        Ec2[j] = pack2(e0, e1);
    }
    float a_cur = __expf(start_trans[cc] + lg[cc]);
    a_sh[0][tid] = a_cur;

    float logscale = 0.f;

    float eb[4];
    #pragma unroll
    for (int jj = 0; jj < 4; jj++) eb[jj] = lg[(1 + jj) * NC + cc];
    __syncthreads();

    int p = 0;

    #define CRF_STEP(T, EMIS)                                                  \
    {                                                                          \
        float ex = __expf(EMIS);                                               \
        float r  = a_sh[p][0];                                                 \
        unsigned long long s0 = 0ull, s1 = 0ull, s2 = 0ull, s3 = 0ull;         \
        _Pragma("unroll")                                                      \
        for (int j = 0; j < 12; j += 2) {                                      \
            ulonglong2 u = *(const ulonglong2*)&a_sh[p][4 * j];                \
            ulonglong2 v = *(const ulonglong2*)&a_sh[p][4 * j + 4];            \
            s0 = ffma2(u.x, Ec2[2 * j],     s0);                               \
            s1 = ffma2(u.y, Ec2[2 * j + 1], s1);                               \
            s2 = ffma2(v.x, Ec2[2 * j + 2], s2);                               \
            s3 = ffma2(v.y, Ec2[2 * j + 3], s3);                               \
        }                                                                      \
        float2 sp = unpack2(fadd2(fadd2(s0, s2), fadd2(s1, s3)));              \
        float s = sp.x + sp.y;                                                 \
        bool rn = ((T) & 127) == 0;                                            \
        float sel = rn ? frcp_fast(r) : 1.0f;                                  \
        logscale += rn ? __logf(r) : 0.0f;                                     \
        float anew = s * ex * sel;                                             \
        a_sh[p ^ 1][tid] = anew;                                               \
        a_cur = anew;                                                          \
        __syncthreads();                                                       \
        p ^= 1;                                                                \
    }

    // main loop: t = 1 .. 1020, groups of 4, no interior branches
    for (int tb = 1; tb + 3 < NT; tb += 4) {
        float en[4];
        #pragma unroll
        for (int jj = 0; jj < 4; jj++) {
            int tt = tb + 4 + jj;
            tt = (tt < NT) ? tt : (NT - 1);
            en[jj] = lg[tt * NC + cc];
        }
        CRF_STEP(tb + 0, eb[0]);
        CRF_STEP(tb + 1, eb[1]);
        CRF_STEP(tb + 2, eb[2]);
        CRF_STEP(tb + 3, eb[3]);
        eb[0] = en[0]; eb[1] = en[1]; eb[2] = en[2]; eb[3] = en[3];
    }
    // epilogue: t = 1021, 1022, 1023
    CRF_STEP(NT - 3, eb[0]);
    CRF_STEP(NT - 2, eb[1]);
    CRF_STEP(NT - 1, eb[2]);
    #undef CRF_STEP

    // ---- logZ + per-chain partial; last block reduces everything ----
    if (tid < NC) red[tid] = a_cur * __expf(end_trans[tid]);
    __syncthreads();
    if (tid == 0) {
        float s = 0.f;
        #pragma unroll
        for (int i = 0; i < NC; i++) s += red[i];
        float logz = __logf(s) + logscale + 4254.5374f;   // + 1023*ln(64)
        g_partial[b] = num - logz;
        __threadfence();
        int v = atomicAdd(&g_done, 1);
        if (v == NB - 1) {                 // last chain: final reduce
            float tot = 0.f;
            #pragma unroll
            for (int i = 0; i < NB; i++) tot += g_partial[i];
            out[out_size - 1] = -tot;
            atomicExch(&g_done, 0);        // reset for graph replay
        }
    }
}

extern "C" void kernel_launch(void* const* d_in, const int* in_sizes, int n_in,
                              void* d_out, int out_size)
{
    const int*   x    = (const int*)  d_in[0];
    const int*   lab  = (const int*)  d_in[1];
    const float* emb  = (const float*)d_in[2];
    const float* fcw  = (const float*)d_in[3];
    const float* fcb  = (const float*)d_in[4];
    const float* st   = (const float*)d_in[5];
    const float* et   = (const float*)d_in[6];
    const float* tr   = (const float*)d_in[7];
    float* out = (float*)d_out;

    cudaFuncSetAttribute(gemm_kernel, cudaFuncAttributeMaxDynamicSharedMemorySize, GEMM_SMEM);
    gemm_kernel<<<NTILES, 128, GEMM_SMEM>>>(x, emb, fcw, fcb, out);
    crf_kernel<<<NB, 64>>>(out, lab, st, et, tr, out, out_size);
}